// round 12
// baseline (speedup 1.0000x reference)
#include <cuda_runtime.h>

#define N_NODES 100000
#define N_EDGES 1600000
#define IN_F 128
#define HID_F 64
#define CLS_F 32
#define NBLK 391   // ceil(N_NODES/256)

// ---------------- scratch (16B-aligned for vector access) ------------------
__device__ __align__(16) float gv56_xw1[N_NODES * HID_F];  // x @ W1 (unscaled)
__device__ __align__(16) float gv56_h1 [N_NODES * HID_F];  // relu(prop1)
__device__ __align__(16) float gv56_hw2s[N_NODES * CLS_F]; // dinv[v]*(h@W2)[v]
__device__ __align__(16) float gv56_dinv[N_NODES];
__device__ int   gv56_cnt[N_NODES];   // zero at entry; re-zeroed by k_scan3
__device__ int   gv56_rowptr[N_NODES + 1];
__device__ int   gv56_cursor[N_NODES];
__device__ int   gv56_col[N_EDGES];
__device__ int   gv56_bsum[512];

// ---------------- per-block edge dtype probe ---------------------------------
__device__ __forceinline__ bool detect_is64(const void* __restrict__ ei) {
    const long long* p = (const long long*)ei;
    bool ok = true;
#pragma unroll
    for (int i = 0; i < 4; i++) {
        long long v = p[i];
        ok &= (v >= 0) && (v < (long long)N_NODES);
    }
    return ok;
}

// ---------------- CSR build --------------------------------------------------
__global__ __launch_bounds__(256) void k_count(const void* __restrict__ ei) {
    __shared__ int s64;
    if (threadIdx.x == 0) s64 = detect_is64(ei) ? 1 : 0;
    __syncthreads();
    const bool is64 = (s64 != 0);
    int e = blockIdx.x * 256 + threadIdx.x;
    if (e < N_EDGES) {
        int d = is64 ? (int)((const long long*)ei)[(long long)N_EDGES + e]
                     : ((const int*)ei)[N_EDGES + e];
        if ((unsigned)d < (unsigned)N_NODES) atomicAdd(&gv56_cnt[d], 1);
    }
}

__global__ __launch_bounds__(256) void k_bsum() {
    __shared__ int red[8];
    int i = blockIdx.x * 256 + threadIdx.x;
    int v = (i < N_NODES) ? gv56_cnt[i] : 0;
#pragma unroll
    for (int o = 16; o; o >>= 1) v += __shfl_down_sync(0xffffffffu, v, o);
    if ((threadIdx.x & 31) == 0) red[threadIdx.x >> 5] = v;
    __syncthreads();
    if (threadIdx.x < 8) {
        int s = red[threadIdx.x];
#pragma unroll
        for (int o = 4; o; o >>= 1) s += __shfl_down_sync(0xffu, s, o);
        if (threadIdx.x == 0) gv56_bsum[blockIdx.x] = s;
    }
}

// per-block scan; offset from bsum; writes rowptr/cursor/dinv; RE-ZEROES cnt
__global__ __launch_bounds__(256) void k_scan3() {
    __shared__ int s[256];
    __shared__ int red[8];
    const int t = threadIdx.x;

    int part = 0;
    for (int j = t; j < blockIdx.x; j += 256) part += gv56_bsum[j];
#pragma unroll
    for (int o = 16; o; o >>= 1) part += __shfl_down_sync(0xffffffffu, part, o);
    if ((t & 31) == 0) red[t >> 5] = part;
    __syncthreads();
    if (t < 8) {
        int sr = red[t];
#pragma unroll
        for (int o = 4; o; o >>= 1) sr += __shfl_down_sync(0xffu, sr, o);
        if (t == 0) red[0] = sr;
    }
    __syncthreads();
    const int off = red[0];

    int i = blockIdx.x * 256 + t;
    int v = (i < N_NODES) ? gv56_cnt[i] : 0;
    s[t] = v;
    __syncthreads();
    for (int o = 1; o < 256; o <<= 1) {
        int a = 0;
        if (t >= o) a = s[t - o];
        __syncthreads();
        s[t] += a;
        __syncthreads();
    }
    if (i < N_NODES) {
        int r = off + s[t] - v;
        gv56_rowptr[i] = r;
        gv56_cursor[i] = r;
        gv56_dinv[i] = rsqrtf((float)(v + 1));
        gv56_cnt[i] = 0;                       // restore invariant for next replay
        if (i == N_NODES - 1) gv56_rowptr[N_NODES] = r + v;
    }
}

__global__ __launch_bounds__(256) void k_fill(const void* __restrict__ ei) {
    __shared__ int s64;
    if (threadIdx.x == 0) s64 = detect_is64(ei) ? 1 : 0;
    __syncthreads();
    const bool is64 = (s64 != 0);
    int e = blockIdx.x * 256 + threadIdx.x;
    if (e < N_EDGES) {
        int s, d;
        if (is64) {
            s = (int)((const long long*)ei)[e];
            d = (int)((const long long*)ei)[(long long)N_EDGES + e];
        } else {
            s = ((const int*)ei)[e];
            d = ((const int*)ei)[N_EDGES + e];
        }
        if ((unsigned)d < (unsigned)N_NODES && (unsigned)s < (unsigned)N_NODES) {
            int slot = atomicAdd(&gv56_cursor[d], 1);
            gv56_col[slot] = s;
        }
    }
}

// ---------------- GEMM1 (R6 winner): xw1 = X @ W1 ----------------------------
__global__ __launch_bounds__(256) void k_gemm1(const float* __restrict__ X,
                                               const float* __restrict__ W) {
    __shared__ __align__(16) float sW[IN_F * HID_F];   // 32 KB
    __shared__ __align__(16) float sX[64 * 36];        // 9 KB

    const int tid = threadIdx.x;
    const int m0 = blockIdx.x * 64;
    const int ty = tid >> 4;
    const int tx = tid & 15;

    for (int i = tid; i < IN_F * HID_F / 4; i += 256)
        ((float4*)sW)[i] = ((const float4*)W)[i];

    float acc[4][4];
#pragma unroll
    for (int i = 0; i < 4; i++)
#pragma unroll
        for (int j = 0; j < 4; j++) acc[i][j] = 0.0f;

    for (int kt = 0; kt < IN_F; kt += 32) {
        __syncthreads();
        for (int i = tid; i < 64 * 8; i += 256) {
            int r = i >> 3, c4 = i & 7;
            int gr = m0 + r;
            float4 v = make_float4(0.f, 0.f, 0.f, 0.f);
            if (gr < N_NODES)
                v = *(const float4*)&X[(size_t)gr * IN_F + kt + c4 * 4];
            *(float4*)&sX[r * 36 + c4 * 4] = v;
        }
        __syncthreads();

#pragma unroll
        for (int kk = 0; kk < 32; kk++) {
            float4 w4 = ((const float4*)(sW + (kt + kk) * HID_F))[tx];
            float a0 = sX[(ty * 4 + 0) * 36 + kk];
            float a1 = sX[(ty * 4 + 1) * 36 + kk];
            float a2 = sX[(ty * 4 + 2) * 36 + kk];
            float a3 = sX[(ty * 4 + 3) * 36 + kk];
            acc[0][0] = fmaf(a0, w4.x, acc[0][0]);
            acc[0][1] = fmaf(a0, w4.y, acc[0][1]);
            acc[0][2] = fmaf(a0, w4.z, acc[0][2]);
            acc[0][3] = fmaf(a0, w4.w, acc[0][3]);
            acc[1][0] = fmaf(a1, w4.x, acc[1][0]);
            acc[1][1] = fmaf(a1, w4.y, acc[1][1]);
            acc[1][2] = fmaf(a1, w4.z, acc[1][2]);
            acc[1][3] = fmaf(a1, w4.w, acc[1][3]);
            acc[2][0] = fmaf(a2, w4.x, acc[2][0]);
            acc[2][1] = fmaf(a2, w4.y, acc[2][1]);
            acc[2][2] = fmaf(a2, w4.z, acc[2][2]);
            acc[2][3] = fmaf(a2, w4.w, acc[2][3]);
            acc[3][0] = fmaf(a3, w4.x, acc[3][0]);
            acc[3][1] = fmaf(a3, w4.y, acc[3][1]);
            acc[3][2] = fmaf(a3, w4.z, acc[3][2]);
            acc[3][3] = fmaf(a3, w4.w, acc[3][3]);
        }
    }

#pragma unroll
    for (int i = 0; i < 4; i++) {
        int gr = m0 + ty * 4 + i;
        if (gr < N_NODES) {
            float4 o = make_float4(acc[i][0], acc[i][1], acc[i][2], acc[i][3]);
            *(float4*)&gv56_xw1[(size_t)gr * HID_F + tx * 4] = o;
        }
    }
}

// ---------------- prop1: h = relu(dv*(dv*xw[v] + sum du*xw[u]) + b1) --------
// warp per node; cols+dinv loaded cooperatively, distributed via shfl.
__global__ __launch_bounds__(256) void k_prop1(const float* __restrict__ b1) {
    const int warp = threadIdx.x >> 5;
    const int lane = threadIdx.x & 31;
    const int v = blockIdx.x * 8 + warp;   // grid = 12500 exactly

    const float2* __restrict__ xw2 = (const float2*)gv56_xw1;
    float dv = gv56_dinv[v];
    float2 self = xw2[(size_t)v * 32 + lane];
    float ax = dv * self.x;
    float ay = dv * self.y;

    int p = gv56_rowptr[v];
    const int e = gv56_rowptr[v + 1];
    while (p < e) {
        int idx = p + lane;
        int c = 0;
        float d = 0.0f;
        if (idx < e) {
            c = gv56_col[idx];
            d = gv56_dinv[c];
        }
        int n = e - p;
        if (n > 32) n = 32;
        for (int j = 0; j < n; j++) {
            int u = __shfl_sync(0xffffffffu, c, j);
            float du = __shfl_sync(0xffffffffu, d, j);
            float2 f = xw2[(size_t)u * 32 + lane];
            ax = fmaf(du, f.x, ax);
            ay = fmaf(du, f.y, ay);
        }
        p += 32;
    }

    float2 bb = ((const float2*)b1)[lane];
    float hx = fmaxf(fmaf(ax, dv, bb.x), 0.0f);
    float hy = fmaxf(fmaf(ay, dv, bb.y), 0.0f);
    ((float2*)gv56_h1)[(size_t)v * 32 + lane] = make_float2(hx, hy);
}

// ---------------- GEMM2: hw2s = dinv * (h1 @ W2) -----------------------------
// 64 rows x 32 cols per block, 256 threads, thread tile 2 rows x 4 cols.
__global__ __launch_bounds__(256) void k_gemm2(const float* __restrict__ W2) {
    __shared__ __align__(16) float sW[HID_F * CLS_F];  // 8 KB
    __shared__ __align__(16) float sX[64 * 68];        // 17.4 KB

    const int tid = threadIdx.x;
    const int m0 = blockIdx.x * 64;
    const int tx = tid & 7;    // col group: cols tx*4 .. +3
    const int ty = tid >> 3;   // 0..31: rows ty*2, ty*2+1

    for (int i = tid; i < HID_F * CLS_F / 4; i += 256)
        ((float4*)sW)[i] = ((const float4*)W2)[i];

    for (int i = tid; i < 64 * 16; i += 256) {
        int r = i >> 4, c4 = i & 15;
        int gr = m0 + r;
        float4 vv = make_float4(0.f, 0.f, 0.f, 0.f);
        if (gr < N_NODES)
            vv = *(const float4*)&gv56_h1[(size_t)gr * HID_F + c4 * 4];
        *(float4*)&sX[r * 68 + c4 * 4] = vv;
    }
    __syncthreads();

    float acc[2][4] = {{0.f, 0.f, 0.f, 0.f}, {0.f, 0.f, 0.f, 0.f}};
#pragma unroll
    for (int k = 0; k < HID_F; k++) {
        float4 w4 = *(const float4*)&sW[k * CLS_F + tx * 4];
        float a0 = sX[(ty * 2 + 0) * 68 + k];
        float a1 = sX[(ty * 2 + 1) * 68 + k];
        acc[0][0] = fmaf(a0, w4.x, acc[0][0]);
        acc[0][1] = fmaf(a0, w4.y, acc[0][1]);
        acc[0][2] = fmaf(a0, w4.z, acc[0][2]);
        acc[0][3] = fmaf(a0, w4.w, acc[0][3]);
        acc[1][0] = fmaf(a1, w4.x, acc[1][0]);
        acc[1][1] = fmaf(a1, w4.y, acc[1][1]);
        acc[1][2] = fmaf(a1, w4.z, acc[1][2]);
        acc[1][3] = fmaf(a1, w4.w, acc[1][3]);
    }

#pragma unroll
    for (int i = 0; i < 2; i++) {
        int gr = m0 + ty * 2 + i;
        if (gr < N_NODES) {
            float dv = gv56_dinv[gr];
            float4 o = make_float4(acc[i][0] * dv, acc[i][1] * dv,
                                   acc[i][2] * dv, acc[i][3] * dv);
            *(float4*)&gv56_hw2s[(size_t)gr * CLS_F + tx * 4] = o;
        }
    }
}

// ---------------- prop2: out[v] = dv*(hw2s[v] + sum hw2s[u]) + b2 -----------
__global__ __launch_bounds__(256) void k_prop2(const float* __restrict__ b2,
                                               float* __restrict__ out) {
    const int warp = threadIdx.x >> 5;
    const int lane = threadIdx.x & 31;
    const int v = blockIdx.x * 8 + warp;   // grid = 12500 exactly

    float dv = gv56_dinv[v];
    float acc = gv56_hw2s[(size_t)v * CLS_F + lane];

    int p = gv56_rowptr[v];
    const int e = gv56_rowptr[v + 1];
    while (p < e) {
        int idx = p + lane;
        int c = 0;
        if (idx < e) c = gv56_col[idx];
        int n = e - p;
        if (n > 32) n = 32;
        for (int j = 0; j < n; j++) {
            int u = __shfl_sync(0xffffffffu, c, j);
            acc += gv56_hw2s[(size_t)u * CLS_F + lane];
        }
        p += 32;
    }
    out[(size_t)v * CLS_F + lane] = fmaf(acc, dv, b2[lane]);
}

// ---------------- launch: fork gemm1 onto side stream ------------------------
extern "C" void kernel_launch(void* const* d_in, const int* in_sizes, int n_in,
                              void* d_out, int out_size) {
    static cudaStream_t s2 = nullptr;
    static cudaEvent_t evFork = nullptr, evGemm = nullptr;
    if (s2 == nullptr) {
        cudaStreamCreateWithFlags(&s2, cudaStreamNonBlocking);
        cudaEventCreateWithFlags(&evFork, cudaEventDisableTiming);
        cudaEventCreateWithFlags(&evGemm, cudaEventDisableTiming);
    }

    const float* x  = nullptr;
    const void*  ei = nullptr;
    const float* W1 = nullptr;
    const float* b1 = nullptr;
    const float* W2 = nullptr;
    const float* b2 = nullptr;

    for (int i = 0; i < n_in; i++) {
        switch (in_sizes[i]) {
            case N_NODES * IN_F:  x  = (const float*)d_in[i]; break;
            case 2 * N_EDGES:     ei = d_in[i];               break;
            case N_EDGES:         /* edge_attr unused */       break;
            case IN_F * HID_F:    W1 = (const float*)d_in[i]; break;
            case HID_F:           b1 = (const float*)d_in[i]; break;
            case HID_F * CLS_F:   W2 = (const float*)d_in[i]; break;
            case CLS_F:           b2 = (const float*)d_in[i]; break;
            default: break;
        }
    }
    if (!x)  x  = (const float*)d_in[0];
    if (!ei) ei = d_in[1];
    if (!W1 && n_in > 3) W1 = (const float*)d_in[3];
    if (!b1 && n_in > 4) b1 = (const float*)d_in[4];
    if (!W2 && n_in > 5) W2 = (const float*)d_in[5];
    if (!b2 && n_in > 6) b2 = (const float*)d_in[6];

    float* out = (float*)d_out;

    // fork: gemm1 ∥ CSR build
    cudaEventRecord(evFork, 0);
    cudaStreamWaitEvent(s2, evFork, 0);
    k_gemm1<<<(N_NODES + 63) / 64, 256, 0, s2>>>(x, W1);
    cudaEventRecord(evGemm, s2);

    k_count<<<(N_EDGES + 255) / 256, 256>>>(ei);
    k_bsum <<<NBLK, 256>>>();
    k_scan3<<<NBLK, 256>>>();
    k_fill <<<(N_EDGES + 255) / 256, 256>>>(ei);

    cudaStreamWaitEvent(0, evGemm, 0);
    k_prop1<<<N_NODES / 8, 256>>>(b1);
    k_gemm2<<<(N_NODES + 63) / 64, 256>>>(W2);
    k_prop2<<<N_NODES / 8, 256>>>(b2, out);
}

// round 13
// speedup vs baseline: 1.0788x; 1.0788x over previous
#include <cuda_runtime.h>

#define N_NODES 100000
#define N_EDGES 1600000
#define IN_F 128
#define HID_F 64
#define CLS_F 32
#define NBLK 391                      // ceil(N_NODES/256)
#define COL_CAP (N_EDGES + 4 * N_NODES)

// ---------------- scratch (16B-aligned; +1 sentinel row, always zero) -------
__device__ __align__(16) float gv56_xw1[N_NODES * HID_F];        // x @ W1
__device__ __align__(16) float gv56_xws[(N_NODES + 1) * HID_F];  // dinv*xw1; row N = 0
__device__ __align__(16) float gv56_h1 [N_NODES * HID_F];
__device__ __align__(16) float gv56_hw2s[(N_NODES + 1) * CLS_F]; // dinv*(h@W2); row N = 0
__device__ __align__(16) float gv56_dinv[N_NODES];
__device__ int   gv56_cnt[N_NODES];   // zero at entry; re-zeroed by k_scan3
__device__ int   gv56_rowptr[N_NODES + 1];
__device__ int   gv56_cursor[N_NODES];
__device__ __align__(16) int gv56_col[COL_CAP];
__device__ int   gv56_bsum[512];

// ---------------- per-block edge dtype probe ---------------------------------
__device__ __forceinline__ bool detect_is64(const void* __restrict__ ei) {
    const long long* p = (const long long*)ei;
    bool ok = true;
#pragma unroll
    for (int i = 0; i < 4; i++) {
        long long v = p[i];
        ok &= (v >= 0) && (v < (long long)N_NODES);
    }
    return ok;
}

// ---------------- CSR build --------------------------------------------------
__global__ __launch_bounds__(256) void k_count(const void* __restrict__ ei) {
    __shared__ int s64;
    if (threadIdx.x == 0) s64 = detect_is64(ei) ? 1 : 0;
    __syncthreads();
    const bool is64 = (s64 != 0);
    int e = blockIdx.x * 256 + threadIdx.x;
    if (e < N_EDGES) {
        int d = is64 ? (int)((const long long*)ei)[(long long)N_EDGES + e]
                     : ((const int*)ei)[N_EDGES + e];
        if ((unsigned)d < (unsigned)N_NODES) atomicAdd(&gv56_cnt[d], 1);
    }
}

// block sums over PADDED counts (each row rounded up to 4)
__global__ __launch_bounds__(256) void k_bsum() {
    __shared__ int red[8];
    int i = blockIdx.x * 256 + threadIdx.x;
    int v = 0;
    if (i < N_NODES) v = (gv56_cnt[i] + 3) & ~3;
#pragma unroll
    for (int o = 16; o; o >>= 1) v += __shfl_down_sync(0xffffffffu, v, o);
    if ((threadIdx.x & 31) == 0) red[threadIdx.x >> 5] = v;
    __syncthreads();
    if (threadIdx.x < 8) {
        int s = red[threadIdx.x];
#pragma unroll
        for (int o = 4; o; o >>= 1) s += __shfl_down_sync(0xffu, s, o);
        if (threadIdx.x == 0) gv56_bsum[blockIdx.x] = s;
    }
}

// scan of padded counts -> rowptr/cursor; dinv from REAL count; sentinel pads;
// re-zeroes cnt for next graph replay.
__global__ __launch_bounds__(256) void k_scan3() {
    __shared__ int s[256];
    __shared__ int red[8];
    const int t = threadIdx.x;

    int part = 0;
    for (int j = t; j < blockIdx.x; j += 256) part += gv56_bsum[j];
#pragma unroll
    for (int o = 16; o; o >>= 1) part += __shfl_down_sync(0xffffffffu, part, o);
    if ((t & 31) == 0) red[t >> 5] = part;
    __syncthreads();
    if (t < 8) {
        int sr = red[t];
#pragma unroll
        for (int o = 4; o; o >>= 1) sr += __shfl_down_sync(0xffu, sr, o);
        if (t == 0) red[0] = sr;
    }
    __syncthreads();
    const int off = red[0];

    int i = blockIdx.x * 256 + t;
    int v = 0, pv = 0;
    if (i < N_NODES) {
        v = gv56_cnt[i];
        pv = (v + 3) & ~3;
    }
    s[t] = pv;
    __syncthreads();
    for (int o = 1; o < 256; o <<= 1) {
        int a = 0;
        if (t >= o) a = s[t - o];
        __syncthreads();
        s[t] += a;
        __syncthreads();
    }
    if (i < N_NODES) {
        int r = off + s[t] - pv;
        gv56_rowptr[i] = r;
        gv56_cursor[i] = r;
        gv56_dinv[i] = rsqrtf((float)(v + 1));
        gv56_cnt[i] = 0;
        // sentinel-pad the tail of this row (<=3 slots)
        for (int q = r + v; q < r + pv; q++) gv56_col[q] = N_NODES;
        if (i == N_NODES - 1) gv56_rowptr[N_NODES] = r + pv;
    }
}

__global__ __launch_bounds__(256) void k_fill(const void* __restrict__ ei) {
    __shared__ int s64;
    if (threadIdx.x == 0) s64 = detect_is64(ei) ? 1 : 0;
    __syncthreads();
    const bool is64 = (s64 != 0);
    int e = blockIdx.x * 256 + threadIdx.x;
    if (e < N_EDGES) {
        int s, d;
        if (is64) {
            s = (int)((const long long*)ei)[e];
            d = (int)((const long long*)ei)[(long long)N_EDGES + e];
        } else {
            s = ((const int*)ei)[e];
            d = ((const int*)ei)[N_EDGES + e];
        }
        if ((unsigned)d < (unsigned)N_NODES && (unsigned)s < (unsigned)N_NODES) {
            int slot = atomicAdd(&gv56_cursor[d], 1);
            gv56_col[slot] = s;
        }
    }
}

// ---------------- GEMM1 (R6 winner): xw1 = X @ W1 ----------------------------
__global__ __launch_bounds__(256) void k_gemm1(const float* __restrict__ X,
                                               const float* __restrict__ W) {
    __shared__ __align__(16) float sW[IN_F * HID_F];   // 32 KB
    __shared__ __align__(16) float sX[64 * 36];        // 9 KB

    const int tid = threadIdx.x;
    const int m0 = blockIdx.x * 64;
    const int ty = tid >> 4;
    const int tx = tid & 15;

    for (int i = tid; i < IN_F * HID_F / 4; i += 256)
        ((float4*)sW)[i] = ((const float4*)W)[i];

    float acc[4][4];
#pragma unroll
    for (int i = 0; i < 4; i++)
#pragma unroll
        for (int j = 0; j < 4; j++) acc[i][j] = 0.0f;

    for (int kt = 0; kt < IN_F; kt += 32) {
        __syncthreads();
        for (int i = tid; i < 64 * 8; i += 256) {
            int r = i >> 3, c4 = i & 7;
            int gr = m0 + r;
            float4 v = make_float4(0.f, 0.f, 0.f, 0.f);
            if (gr < N_NODES)
                v = *(const float4*)&X[(size_t)gr * IN_F + kt + c4 * 4];
            *(float4*)&sX[r * 36 + c4 * 4] = v;
        }
        __syncthreads();

#pragma unroll
        for (int kk = 0; kk < 32; kk++) {
            float4 w4 = ((const float4*)(sW + (kt + kk) * HID_F))[tx];
            float a0 = sX[(ty * 4 + 0) * 36 + kk];
            float a1 = sX[(ty * 4 + 1) * 36 + kk];
            float a2 = sX[(ty * 4 + 2) * 36 + kk];
            float a3 = sX[(ty * 4 + 3) * 36 + kk];
            acc[0][0] = fmaf(a0, w4.x, acc[0][0]);
            acc[0][1] = fmaf(a0, w4.y, acc[0][1]);
            acc[0][2] = fmaf(a0, w4.z, acc[0][2]);
            acc[0][3] = fmaf(a0, w4.w, acc[0][3]);
            acc[1][0] = fmaf(a1, w4.x, acc[1][0]);
            acc[1][1] = fmaf(a1, w4.y, acc[1][1]);
            acc[1][2] = fmaf(a1, w4.z, acc[1][2]);
            acc[1][3] = fmaf(a1, w4.w, acc[1][3]);
            acc[2][0] = fmaf(a2, w4.x, acc[2][0]);
            acc[2][1] = fmaf(a2, w4.y, acc[2][1]);
            acc[2][2] = fmaf(a2, w4.z, acc[2][2]);
            acc[2][3] = fmaf(a2, w4.w, acc[2][3]);
            acc[3][0] = fmaf(a3, w4.x, acc[3][0]);
            acc[3][1] = fmaf(a3, w4.y, acc[3][1]);
            acc[3][2] = fmaf(a3, w4.z, acc[3][2]);
            acc[3][3] = fmaf(a3, w4.w, acc[3][3]);
        }
    }

#pragma unroll
    for (int i = 0; i < 4; i++) {
        int gr = m0 + ty * 4 + i;
        if (gr < N_NODES) {
            float4 o = make_float4(acc[i][0], acc[i][1], acc[i][2], acc[i][3]);
            *(float4*)&gv56_xw1[(size_t)gr * HID_F + tx * 4] = o;
        }
    }
}

// ---------------- scale: xws = dinv ⊙ xw1 (join kernel) ----------------------
__global__ __launch_bounds__(256) void k_scale() {
    int i = blockIdx.x * 256 + threadIdx.x;         // float4 index; grid 6250
    int row = i >> 4;                                // 16 float4 per row
    float dv = gv56_dinv[row];
    float4 v = ((const float4*)gv56_xw1)[i];
    v.x *= dv; v.y *= dv; v.z *= dv; v.w *= dv;
    ((float4*)gv56_xws)[i] = v;
}

// ---------------- prop1: h = relu(dv*(xws[v] + sum xws[u]) + b1) -------------
// warp per node; rows 4-aligned; col via uniform int4; sentinel rows are zero.
__global__ __launch_bounds__(256) void k_prop1(const float* __restrict__ b1) {
    const int warp = threadIdx.x >> 5;
    const int lane = threadIdx.x & 31;
    const int v = blockIdx.x * 8 + warp;            // grid 12500 exact

    const float2* __restrict__ xw2 = (const float2*)gv56_xws;
    float dv = gv56_dinv[v];
    float2 self = xw2[(size_t)v * 32 + lane];
    float ax = self.x;
    float ay = self.y;

    int p = gv56_rowptr[v];
    const int e = gv56_rowptr[v + 1];               // (e - p) % 4 == 0
    for (; p + 8 <= e; p += 8) {
        int4 c0 = *(const int4*)&gv56_col[p];
        int4 c1 = *(const int4*)&gv56_col[p + 4];
        float2 f0 = xw2[(size_t)c0.x * 32 + lane];
        float2 f1 = xw2[(size_t)c0.y * 32 + lane];
        float2 f2 = xw2[(size_t)c0.z * 32 + lane];
        float2 f3 = xw2[(size_t)c0.w * 32 + lane];
        float2 f4 = xw2[(size_t)c1.x * 32 + lane];
        float2 f5 = xw2[(size_t)c1.y * 32 + lane];
        float2 f6 = xw2[(size_t)c1.z * 32 + lane];
        float2 f7 = xw2[(size_t)c1.w * 32 + lane];
        ax += f0.x + f1.x + f2.x + f3.x + f4.x + f5.x + f6.x + f7.x;
        ay += f0.y + f1.y + f2.y + f3.y + f4.y + f5.y + f6.y + f7.y;
    }
    if (p < e) {                                    // exactly one int4 group
        int4 c0 = *(const int4*)&gv56_col[p];
        float2 f0 = xw2[(size_t)c0.x * 32 + lane];
        float2 f1 = xw2[(size_t)c0.y * 32 + lane];
        float2 f2 = xw2[(size_t)c0.z * 32 + lane];
        float2 f3 = xw2[(size_t)c0.w * 32 + lane];
        ax += f0.x + f1.x + f2.x + f3.x;
        ay += f0.y + f1.y + f2.y + f3.y;
    }

    float2 bb = ((const float2*)b1)[lane];
    float hx = fmaxf(fmaf(ax, dv, bb.x), 0.0f);
    float hy = fmaxf(fmaf(ay, dv, bb.y), 0.0f);
    ((float2*)gv56_h1)[(size_t)v * 32 + lane] = make_float2(hx, hy);
}

// ---------------- GEMM2: hw2s = dinv ⊙ (h1 @ W2) -----------------------------
__global__ __launch_bounds__(256) void k_gemm2(const float* __restrict__ W2) {
    __shared__ __align__(16) float sW[HID_F * CLS_F];  // 8 KB
    __shared__ __align__(16) float sX[64 * 68];        // 17.4 KB

    const int tid = threadIdx.x;
    const int m0 = blockIdx.x * 64;
    const int tx = tid & 7;
    const int ty = tid >> 3;

    for (int i = tid; i < HID_F * CLS_F / 4; i += 256)
        ((float4*)sW)[i] = ((const float4*)W2)[i];

    for (int i = tid; i < 64 * 16; i += 256) {
        int r = i >> 4, c4 = i & 15;
        int gr = m0 + r;
        float4 vv = make_float4(0.f, 0.f, 0.f, 0.f);
        if (gr < N_NODES)
            vv = *(const float4*)&gv56_h1[(size_t)gr * HID_F + c4 * 4];
        *(float4*)&sX[r * 68 + c4 * 4] = vv;
    }
    __syncthreads();

    float acc[2][4] = {{0.f, 0.f, 0.f, 0.f}, {0.f, 0.f, 0.f, 0.f}};
#pragma unroll
    for (int k = 0; k < HID_F; k++) {
        float4 w4 = *(const float4*)&sW[k * CLS_F + tx * 4];
        float a0 = sX[(ty * 2 + 0) * 68 + k];
        float a1 = sX[(ty * 2 + 1) * 68 + k];
        acc[0][0] = fmaf(a0, w4.x, acc[0][0]);
        acc[0][1] = fmaf(a0, w4.y, acc[0][1]);
        acc[0][2] = fmaf(a0, w4.z, acc[0][2]);
        acc[0][3] = fmaf(a0, w4.w, acc[0][3]);
        acc[1][0] = fmaf(a1, w4.x, acc[1][0]);
        acc[1][1] = fmaf(a1, w4.y, acc[1][1]);
        acc[1][2] = fmaf(a1, w4.z, acc[1][2]);
        acc[1][3] = fmaf(a1, w4.w, acc[1][3]);
    }

#pragma unroll
    for (int i = 0; i < 2; i++) {
        int gr = m0 + ty * 2 + i;
        if (gr < N_NODES) {
            float dv = gv56_dinv[gr];
            float4 o = make_float4(acc[i][0] * dv, acc[i][1] * dv,
                                   acc[i][2] * dv, acc[i][3] * dv);
            *(float4*)&gv56_hw2s[(size_t)gr * CLS_F + tx * 4] = o;
        }
    }
}

// ---------------- prop2: out[v] = dv*(hw2s[v] + sum hw2s[u]) + b2 ------------
__global__ __launch_bounds__(256) void k_prop2(const float* __restrict__ b2,
                                               float* __restrict__ out) {
    const int warp = threadIdx.x >> 5;
    const int lane = threadIdx.x & 31;
    const int v = blockIdx.x * 8 + warp;            // grid 12500 exact

    float dv = gv56_dinv[v];
    float acc = gv56_hw2s[(size_t)v * CLS_F + lane];

    int p = gv56_rowptr[v];
    const int e = gv56_rowptr[v + 1];
    for (; p + 8 <= e; p += 8) {
        int4 c0 = *(const int4*)&gv56_col[p];
        int4 c1 = *(const int4*)&gv56_col[p + 4];
        float f0 = gv56_hw2s[(size_t)c0.x * CLS_F + lane];
        float f1 = gv56_hw2s[(size_t)c0.y * CLS_F + lane];
        float f2 = gv56_hw2s[(size_t)c0.z * CLS_F + lane];
        float f3 = gv56_hw2s[(size_t)c0.w * CLS_F + lane];
        float f4 = gv56_hw2s[(size_t)c1.x * CLS_F + lane];
        float f5 = gv56_hw2s[(size_t)c1.y * CLS_F + lane];
        float f6 = gv56_hw2s[(size_t)c1.z * CLS_F + lane];
        float f7 = gv56_hw2s[(size_t)c1.w * CLS_F + lane];
        acc += f0 + f1 + f2 + f3 + f4 + f5 + f6 + f7;
    }
    if (p < e) {
        int4 c0 = *(const int4*)&gv56_col[p];
        acc += gv56_hw2s[(size_t)c0.x * CLS_F + lane]
             + gv56_hw2s[(size_t)c0.y * CLS_F + lane]
             + gv56_hw2s[(size_t)c0.z * CLS_F + lane]
             + gv56_hw2s[(size_t)c0.w * CLS_F + lane];
    }
    out[(size_t)v * CLS_F + lane] = fmaf(acc, dv, b2[lane]);
}

// ---------------- launch: fork gemm1 onto side stream ------------------------
extern "C" void kernel_launch(void* const* d_in, const int* in_sizes, int n_in,
                              void* d_out, int out_size) {
    static cudaStream_t s2 = nullptr;
    static cudaEvent_t evFork = nullptr, evGemm = nullptr;
    if (s2 == nullptr) {
        cudaStreamCreateWithFlags(&s2, cudaStreamNonBlocking);
        cudaEventCreateWithFlags(&evFork, cudaEventDisableTiming);
        cudaEventCreateWithFlags(&evGemm, cudaEventDisableTiming);
    }

    const float* x  = nullptr;
    const void*  ei = nullptr;
    const float* W1 = nullptr;
    const float* b1 = nullptr;
    const float* W2 = nullptr;
    const float* b2 = nullptr;

    for (int i = 0; i < n_in; i++) {
        switch (in_sizes[i]) {
            case N_NODES * IN_F:  x  = (const float*)d_in[i]; break;
            case 2 * N_EDGES:     ei = d_in[i];               break;
            case N_EDGES:         /* edge_attr unused */       break;
            case IN_F * HID_F:    W1 = (const float*)d_in[i]; break;
            case HID_F:           b1 = (const float*)d_in[i]; break;
            case HID_F * CLS_F:   W2 = (const float*)d_in[i]; break;
            case CLS_F:           b2 = (const float*)d_in[i]; break;
            default: break;
        }
    }
    if (!x)  x  = (const float*)d_in[0];
    if (!ei) ei = d_in[1];
    if (!W1 && n_in > 3) W1 = (const float*)d_in[3];
    if (!b1 && n_in > 4) b1 = (const float*)d_in[4];
    if (!W2 && n_in > 5) W2 = (const float*)d_in[5];
    if (!b2 && n_in > 6) b2 = (const float*)d_in[6];

    float* out = (float*)d_out;

    // fork: gemm1 ∥ CSR build
    cudaEventRecord(evFork, 0);
    cudaStreamWaitEvent(s2, evFork, 0);
    k_gemm1<<<(N_NODES + 63) / 64, 256, 0, s2>>>(x, W1);
    cudaEventRecord(evGemm, s2);

    k_count<<<(N_EDGES + 255) / 256, 256>>>(ei);
    k_bsum <<<NBLK, 256>>>();
    k_scan3<<<NBLK, 256>>>();
    k_fill <<<(N_EDGES + 255) / 256, 256>>>(ei);

    // join: scale needs gemm1 (xw1) + scan3 (dinv)
    cudaStreamWaitEvent(0, evGemm, 0);
    k_scale<<<N_NODES * HID_F / 4 / 256, 256>>>();
    k_prop1<<<N_NODES / 8, 256>>>(b1);
    k_gemm2<<<(N_NODES + 63) / 64, 256>>>(W2);
    k_prop2<<<N_NODES / 8, 256>>>(b2, out);
}

// round 14
// speedup vs baseline: 1.1068x; 1.0259x over previous
#include <cuda_runtime.h>

#define N_NODES 100000
#define N_EDGES 1600000
#define IN_F 128
#define HID_F 64
#define CLS_F 32
#define NBLK 391                      // ceil(N_NODES/256)
#define COL_CAP (N_EDGES + 4 * N_NODES)

// ---------------- scratch (16B-aligned; +1 sentinel row, always zero) -------
__device__ __align__(16) float gv56_xw1[N_NODES * HID_F];        // x @ W1
__device__ __align__(16) float gv56_xws[(N_NODES + 1) * HID_F];  // dinv*xw1; row N = 0
__device__ __align__(16) float gv56_h1 [N_NODES * HID_F];
__device__ __align__(16) float gv56_hw2s[(N_NODES + 1) * CLS_F]; // dinv*(h@W2); row N = 0
__device__ __align__(16) float gv56_dinv[N_NODES];
__device__ int   gv56_cnt[N_NODES];   // zero at entry; re-zeroed by k_scan
__device__ int   gv56_rowptr[N_NODES + 1];
__device__ int   gv56_cursor[N_NODES];
__device__ __align__(16) int gv56_col[COL_CAP];
__device__ unsigned long long gv56_lb[512];   // lookback: (flag<<32)|agg; zeroed by k_count

// ---------------- per-block edge dtype probe ---------------------------------
__device__ __forceinline__ bool detect_is64(const void* __restrict__ ei) {
    const long long* p = (const long long*)ei;
    bool ok = true;
#pragma unroll
    for (int i = 0; i < 4; i++) {
        long long v = p[i];
        ok &= (v >= 0) && (v < (long long)N_NODES);
    }
    return ok;
}

// ---------------- count: degrees + zero lookback flags ------------------------
// 4 edges per thread; grid = 1563
__global__ __launch_bounds__(256) void k_count(const void* __restrict__ ei) {
    __shared__ int s64;
    if (threadIdx.x == 0) s64 = detect_is64(ei) ? 1 : 0;
    // blocks 0,1 zero the lookback array (512 words)
    if (blockIdx.x < 2) {
        int idx = blockIdx.x * 256 + threadIdx.x;
        gv56_lb[idx] = 0ull;
    }
    __syncthreads();
    const bool is64 = (s64 != 0);
    int e0 = (blockIdx.x * 256 + threadIdx.x) * 4;
    if (e0 >= N_EDGES) return;
    int d[4];
    if (is64) {
        const long long* p = (const long long*)ei;
#pragma unroll
        for (int i = 0; i < 4; i++)
            d[i] = (e0 + i < N_EDGES) ? (int)p[(long long)N_EDGES + e0 + i] : -1;
    } else {
        int4 dd = *(const int4*)&((const int*)ei)[N_EDGES + e0];  // N_EDGES%4==0, e0%4==0
        d[0] = dd.x; d[1] = dd.y; d[2] = dd.z; d[3] = dd.w;
#pragma unroll
        for (int i = 0; i < 4; i++)
            if (e0 + i >= N_EDGES) d[i] = -1;
    }
#pragma unroll
    for (int i = 0; i < 4; i++)
        if ((unsigned)d[i] < (unsigned)N_NODES) atomicAdd(&gv56_cnt[d[i]], 1);
}

// ---------------- single-pass lookback scan -----------------------------------
// padded counts -> rowptr/cursor; dinv from real count; sentinel pads; re-zero cnt
__global__ __launch_bounds__(256) void k_scan(int dummy) {
    __shared__ int s[256];
    __shared__ int red[8];
    const int t = threadIdx.x;
    const int b = blockIdx.x;

    int i = b * 256 + t;
    int v = 0, pv = 0;
    if (i < N_NODES) {
        v = gv56_cnt[i];
        pv = (v + 3) & ~3;
    }

    // block aggregate of padded counts
    int agg = pv;
#pragma unroll
    for (int o = 16; o; o >>= 1) agg += __shfl_down_sync(0xffffffffu, agg, o);
    if ((t & 31) == 0) red[t >> 5] = agg;
    __syncthreads();
    if (t < 8) {
        int sr = red[t];
#pragma unroll
        for (int o = 4; o; o >>= 1) sr += __shfl_down_sync(0xffu, sr, o);
        if (t == 0) {
            red[0] = sr;
            gv56_lb[b] = (1ull << 32) | (unsigned long long)(unsigned)sr;  // publish
        }
    }
    __syncthreads();

    // lookback: sum predecessor aggregates (all blocks co-resident: 391 < 1184)
    int part = 0;
    for (int j = t; j < b; j += 256) {
        unsigned long long w;
        do {
            w = *((volatile unsigned long long*)&gv56_lb[j]);
        } while ((w >> 32) == 0ull);
        part += (int)(unsigned)w;
    }
#pragma unroll
    for (int o = 16; o; o >>= 1) part += __shfl_down_sync(0xffffffffu, part, o);
    if ((t & 31) == 0) red[t >> 5] = part;
    __syncthreads();
    if (t < 8) {
        int sr = red[t];
#pragma unroll
        for (int o = 4; o; o >>= 1) sr += __shfl_down_sync(0xffu, sr, o);
        if (t == 0) red[0] = sr;
    }
    __syncthreads();
    const int off = red[0];

    // local exclusive scan of padded counts
    s[t] = pv;
    __syncthreads();
    for (int o = 1; o < 256; o <<= 1) {
        int a = 0;
        if (t >= o) a = s[t - o];
        __syncthreads();
        s[t] += a;
        __syncthreads();
    }
    if (i < N_NODES) {
        int r = off + s[t] - pv;
        gv56_rowptr[i] = r;
        gv56_cursor[i] = r;
        gv56_dinv[i] = rsqrtf((float)(v + 1));
        gv56_cnt[i] = 0;
        for (int q = r + v; q < r + pv; q++) gv56_col[q] = N_NODES;
        if (i == N_NODES - 1) gv56_rowptr[N_NODES] = r + pv;
    }
}

// ---------------- fill: 4 edges per thread ------------------------------------
__global__ __launch_bounds__(256) void k_fill(const void* __restrict__ ei) {
    __shared__ int s64;
    if (threadIdx.x == 0) s64 = detect_is64(ei) ? 1 : 0;
    __syncthreads();
    const bool is64 = (s64 != 0);
    int e0 = (blockIdx.x * 256 + threadIdx.x) * 4;
    if (e0 >= N_EDGES) return;
    int sarr[4], darr[4];
    if (is64) {
        const long long* p = (const long long*)ei;
#pragma unroll
        for (int i = 0; i < 4; i++) {
            if (e0 + i < N_EDGES) {
                sarr[i] = (int)p[e0 + i];
                darr[i] = (int)p[(long long)N_EDGES + e0 + i];
            } else { sarr[i] = -1; darr[i] = -1; }
        }
    } else {
        int4 ss = *(const int4*)&((const int*)ei)[e0];
        int4 dd = *(const int4*)&((const int*)ei)[N_EDGES + e0];
        sarr[0] = ss.x; sarr[1] = ss.y; sarr[2] = ss.z; sarr[3] = ss.w;
        darr[0] = dd.x; darr[1] = dd.y; darr[2] = dd.z; darr[3] = dd.w;
#pragma unroll
        for (int i = 0; i < 4; i++)
            if (e0 + i >= N_EDGES) { sarr[i] = -1; darr[i] = -1; }
    }
#pragma unroll
    for (int i = 0; i < 4; i++) {
        if ((unsigned)darr[i] < (unsigned)N_NODES &&
            (unsigned)sarr[i] < (unsigned)N_NODES) {
            int slot = atomicAdd(&gv56_cursor[darr[i]], 1);
            gv56_col[slot] = sarr[i];
        }
    }
}

// ---------------- GEMM1 (R6 winner): xw1 = X @ W1 ----------------------------
__global__ __launch_bounds__(256) void k_gemm1(const float* __restrict__ X,
                                               const float* __restrict__ W) {
    __shared__ __align__(16) float sW[IN_F * HID_F];   // 32 KB
    __shared__ __align__(16) float sX[64 * 36];        // 9 KB

    const int tid = threadIdx.x;
    const int m0 = blockIdx.x * 64;
    const int ty = tid >> 4;
    const int tx = tid & 15;

    for (int i = tid; i < IN_F * HID_F / 4; i += 256)
        ((float4*)sW)[i] = ((const float4*)W)[i];

    float acc[4][4];
#pragma unroll
    for (int i = 0; i < 4; i++)
#pragma unroll
        for (int j = 0; j < 4; j++) acc[i][j] = 0.0f;

    for (int kt = 0; kt < IN_F; kt += 32) {
        __syncthreads();
        for (int i = tid; i < 64 * 8; i += 256) {
            int r = i >> 3, c4 = i & 7;
            int gr = m0 + r;
            float4 v = make_float4(0.f, 0.f, 0.f, 0.f);
            if (gr < N_NODES)
                v = *(const float4*)&X[(size_t)gr * IN_F + kt + c4 * 4];
            *(float4*)&sX[r * 36 + c4 * 4] = v;
        }
        __syncthreads();

#pragma unroll
        for (int kk = 0; kk < 32; kk++) {
            float4 w4 = ((const float4*)(sW + (kt + kk) * HID_F))[tx];
            float a0 = sX[(ty * 4 + 0) * 36 + kk];
            float a1 = sX[(ty * 4 + 1) * 36 + kk];
            float a2 = sX[(ty * 4 + 2) * 36 + kk];
            float a3 = sX[(ty * 4 + 3) * 36 + kk];
            acc[0][0] = fmaf(a0, w4.x, acc[0][0]);
            acc[0][1] = fmaf(a0, w4.y, acc[0][1]);
            acc[0][2] = fmaf(a0, w4.z, acc[0][2]);
            acc[0][3] = fmaf(a0, w4.w, acc[0][3]);
            acc[1][0] = fmaf(a1, w4.x, acc[1][0]);
            acc[1][1] = fmaf(a1, w4.y, acc[1][1]);
            acc[1][2] = fmaf(a1, w4.z, acc[1][2]);
            acc[1][3] = fmaf(a1, w4.w, acc[1][3]);
            acc[2][0] = fmaf(a2, w4.x, acc[2][0]);
            acc[2][1] = fmaf(a2, w4.y, acc[2][1]);
            acc[2][2] = fmaf(a2, w4.z, acc[2][2]);
            acc[2][3] = fmaf(a2, w4.w, acc[2][3]);
            acc[3][0] = fmaf(a3, w4.x, acc[3][0]);
            acc[3][1] = fmaf(a3, w4.y, acc[3][1]);
            acc[3][2] = fmaf(a3, w4.z, acc[3][2]);
            acc[3][3] = fmaf(a3, w4.w, acc[3][3]);
        }
    }

#pragma unroll
    for (int i = 0; i < 4; i++) {
        int gr = m0 + ty * 4 + i;
        if (gr < N_NODES) {
            float4 o = make_float4(acc[i][0], acc[i][1], acc[i][2], acc[i][3]);
            *(float4*)&gv56_xw1[(size_t)gr * HID_F + tx * 4] = o;
        }
    }
}

// ---------------- scale: xws = dinv ⊙ xw1 ------------------------------------
__global__ __launch_bounds__(256) void k_scale() {
    int i = blockIdx.x * 256 + threadIdx.x;   // float4 index; grid 6250
    int row = i >> 4;
    float dv = gv56_dinv[row];
    float4 v = ((const float4*)gv56_xw1)[i];
    v.x *= dv; v.y *= dv; v.z *= dv; v.w *= dv;
    ((float4*)gv56_xws)[i] = v;
}

// ---------------- prop1: h = relu(dv*(xws[v] + sum xws[u]) + b1) -------------
__global__ __launch_bounds__(256) void k_prop1(const float* __restrict__ b1) {
    const int warp = threadIdx.x >> 5;
    const int lane = threadIdx.x & 31;
    const int v = blockIdx.x * 8 + warp;      // grid 12500 exact

    const float2* __restrict__ xw2 = (const float2*)gv56_xws;
    float dv = gv56_dinv[v];
    float2 self = xw2[(size_t)v * 32 + lane];
    float ax = self.x;
    float ay = self.y;

    int p = gv56_rowptr[v];
    const int e = gv56_rowptr[v + 1];         // (e - p) % 4 == 0
    for (; p + 8 <= e; p += 8) {
        int4 c0 = *(const int4*)&gv56_col[p];
        int4 c1 = *(const int4*)&gv56_col[p + 4];
        float2 f0 = xw2[(size_t)c0.x * 32 + lane];
        float2 f1 = xw2[(size_t)c0.y * 32 + lane];
        float2 f2 = xw2[(size_t)c0.z * 32 + lane];
        float2 f3 = xw2[(size_t)c0.w * 32 + lane];
        float2 f4 = xw2[(size_t)c1.x * 32 + lane];
        float2 f5 = xw2[(size_t)c1.y * 32 + lane];
        float2 f6 = xw2[(size_t)c1.z * 32 + lane];
        float2 f7 = xw2[(size_t)c1.w * 32 + lane];
        ax += f0.x + f1.x + f2.x + f3.x + f4.x + f5.x + f6.x + f7.x;
        ay += f0.y + f1.y + f2.y + f3.y + f4.y + f5.y + f6.y + f7.y;
    }
    if (p < e) {
        int4 c0 = *(const int4*)&gv56_col[p];
        float2 f0 = xw2[(size_t)c0.x * 32 + lane];
        float2 f1 = xw2[(size_t)c0.y * 32 + lane];
        float2 f2 = xw2[(size_t)c0.z * 32 + lane];
        float2 f3 = xw2[(size_t)c0.w * 32 + lane];
        ax += f0.x + f1.x + f2.x + f3.x;
        ay += f0.y + f1.y + f2.y + f3.y;
    }

    float2 bb = ((const float2*)b1)[lane];
    float hx = fmaxf(fmaf(ax, dv, bb.x), 0.0f);
    float hy = fmaxf(fmaf(ay, dv, bb.y), 0.0f);
    ((float2*)gv56_h1)[(size_t)v * 32 + lane] = make_float2(hx, hy);
}

// ---------------- GEMM2: hw2s = dinv ⊙ (h1 @ W2) -----------------------------
__global__ __launch_bounds__(256) void k_gemm2(const float* __restrict__ W2) {
    __shared__ __align__(16) float sW[HID_F * CLS_F];  // 8 KB
    __shared__ __align__(16) float sX[64 * 68];        // 17.4 KB

    const int tid = threadIdx.x;
    const int m0 = blockIdx.x * 64;
    const int tx = tid & 7;
    const int ty = tid >> 3;

    for (int i = tid; i < HID_F * CLS_F / 4; i += 256)
        ((float4*)sW)[i] = ((const float4*)W2)[i];

    for (int i = tid; i < 64 * 16; i += 256) {
        int r = i >> 4, c4 = i & 15;
        int gr = m0 + r;
        float4 vv = make_float4(0.f, 0.f, 0.f, 0.f);
        if (gr < N_NODES)
            vv = *(const float4*)&gv56_h1[(size_t)gr * HID_F + c4 * 4];
        *(float4*)&sX[r * 68 + c4 * 4] = vv;
    }
    __syncthreads();

    float acc[2][4] = {{0.f, 0.f, 0.f, 0.f}, {0.f, 0.f, 0.f, 0.f}};
#pragma unroll
    for (int k = 0; k < HID_F; k++) {
        float4 w4 = *(const float4*)&sW[k * CLS_F + tx * 4];
        float a0 = sX[(ty * 2 + 0) * 68 + k];
        float a1 = sX[(ty * 2 + 1) * 68 + k];
        acc[0][0] = fmaf(a0, w4.x, acc[0][0]);
        acc[0][1] = fmaf(a0, w4.y, acc[0][1]);
        acc[0][2] = fmaf(a0, w4.z, acc[0][2]);
        acc[0][3] = fmaf(a0, w4.w, acc[0][3]);
        acc[1][0] = fmaf(a1, w4.x, acc[1][0]);
        acc[1][1] = fmaf(a1, w4.y, acc[1][1]);
        acc[1][2] = fmaf(a1, w4.z, acc[1][2]);
        acc[1][3] = fmaf(a1, w4.w, acc[1][3]);
    }

#pragma unroll
    for (int i = 0; i < 2; i++) {
        int gr = m0 + ty * 2 + i;
        if (gr < N_NODES) {
            float dv = gv56_dinv[gr];
            float4 o = make_float4(acc[i][0] * dv, acc[i][1] * dv,
                                   acc[i][2] * dv, acc[i][3] * dv);
            *(float4*)&gv56_hw2s[(size_t)gr * CLS_F + tx * 4] = o;
        }
    }
}

// ---------------- prop2: out[v] = dv*(hw2s[v] + sum hw2s[u]) + b2 ------------
__global__ __launch_bounds__(256) void k_prop2(const float* __restrict__ b2,
                                               float* __restrict__ out) {
    const int warp = threadIdx.x >> 5;
    const int lane = threadIdx.x & 31;
    const int v = blockIdx.x * 8 + warp;      // grid 12500 exact

    float dv = gv56_dinv[v];
    float acc = gv56_hw2s[(size_t)v * CLS_F + lane];

    int p = gv56_rowptr[v];
    const int e = gv56_rowptr[v + 1];
    for (; p + 8 <= e; p += 8) {
        int4 c0 = *(const int4*)&gv56_col[p];
        int4 c1 = *(const int4*)&gv56_col[p + 4];
        float f0 = gv56_hw2s[(size_t)c0.x * CLS_F + lane];
        float f1 = gv56_hw2s[(size_t)c0.y * CLS_F + lane];
        float f2 = gv56_hw2s[(size_t)c0.z * CLS_F + lane];
        float f3 = gv56_hw2s[(size_t)c0.w * CLS_F + lane];
        float f4 = gv56_hw2s[(size_t)c1.x * CLS_F + lane];
        float f5 = gv56_hw2s[(size_t)c1.y * CLS_F + lane];
        float f6 = gv56_hw2s[(size_t)c1.z * CLS_F + lane];
        float f7 = gv56_hw2s[(size_t)c1.w * CLS_F + lane];
        acc += f0 + f1 + f2 + f3 + f4 + f5 + f6 + f7;
    }
    if (p < e) {
        int4 c0 = *(const int4*)&gv56_col[p];
        acc += gv56_hw2s[(size_t)c0.x * CLS_F + lane]
             + gv56_hw2s[(size_t)c0.y * CLS_F + lane]
             + gv56_hw2s[(size_t)c0.z * CLS_F + lane]
             + gv56_hw2s[(size_t)c0.w * CLS_F + lane];
    }
    out[(size_t)v * CLS_F + lane] = fmaf(acc, dv, b2[lane]);
}

// ---------------- launch ------------------------------------------------------
extern "C" void kernel_launch(void* const* d_in, const int* in_sizes, int n_in,
                              void* d_out, int out_size) {
    static cudaStream_t s2 = nullptr;
    static cudaEvent_t evFork = nullptr, evScan = nullptr, evScale = nullptr;
    if (s2 == nullptr) {
        int loPri = 0, hiPri = 0;
        cudaDeviceGetStreamPriorityRange(&loPri, &hiPri);
        cudaStreamCreateWithPriority(&s2, cudaStreamNonBlocking, hiPri);
        cudaEventCreateWithFlags(&evFork, cudaEventDisableTiming);
        cudaEventCreateWithFlags(&evScan, cudaEventDisableTiming);
        cudaEventCreateWithFlags(&evScale, cudaEventDisableTiming);
    }

    const float* x  = nullptr;
    const void*  ei = nullptr;
    const float* W1 = nullptr;
    const float* b1 = nullptr;
    const float* W2 = nullptr;
    const float* b2 = nullptr;

    for (int i = 0; i < n_in; i++) {
        switch (in_sizes[i]) {
            case N_NODES * IN_F:  x  = (const float*)d_in[i]; break;
            case 2 * N_EDGES:     ei = d_in[i];               break;
            case N_EDGES:         /* edge_attr unused */       break;
            case IN_F * HID_F:    W1 = (const float*)d_in[i]; break;
            case HID_F:           b1 = (const float*)d_in[i]; break;
            case HID_F * CLS_F:   W2 = (const float*)d_in[i]; break;
            case CLS_F:           b2 = (const float*)d_in[i]; break;
            default: break;
        }
    }
    if (!x)  x  = (const float*)d_in[0];
    if (!ei) ei = d_in[1];
    if (!W1 && n_in > 3) W1 = (const float*)d_in[3];
    if (!b1 && n_in > 4) b1 = (const float*)d_in[4];
    if (!W2 && n_in > 5) W2 = (const float*)d_in[5];
    if (!b2 && n_in > 6) b2 = (const float*)d_in[6];

    float* out = (float*)d_out;

    // fork: gemm1 (high-priority s2) ∥ CSR build (main)
    cudaEventRecord(evFork, 0);
    cudaStreamWaitEvent(s2, evFork, 0);
    k_gemm1<<<(N_NODES + 63) / 64, 256, 0, s2>>>(x, W1);

    k_count<<<(N_EDGES / 4 + 255) / 256, 256>>>(ei);   // also zeroes lookback flags
    k_scan <<<NBLK, 256>>>(0);                         // single-pass lookback scan
    cudaEventRecord(evScan, 0);
    // scale on s2 after gemm1 + scan (overlaps with fill on main)
    cudaStreamWaitEvent(s2, evScan, 0);
    k_scale<<<N_NODES * HID_F / 4 / 256, 256, 0, s2>>>();
    cudaEventRecord(evScale, s2);

    k_fill <<<(N_EDGES / 4 + 255) / 256, 256>>>(ei);

    // join: prop chain needs fill (main, in-order) + scale (s2 event)
    cudaStreamWaitEvent(0, evScale, 0);
    k_prop1<<<N_NODES / 8, 256>>>(b1);
    k_gemm2<<<(N_NODES + 63) / 64, 256>>>(W2);
    k_prop2<<<N_NODES / 8, 256>>>(b2, out);
}